// round 6
// baseline (speedup 1.0000x reference)
#include <cuda_runtime.h>

// RNNBlock: out = relu( RNN_backwards(x; w_in, w_rec, b_rnn) @ w_d + b_d )
// fp32 exact, packed f32x2 FMA. R6: h loaded as k-pair LDS.64 (halves smem
// cycles -> FMA sole binder), single barrier per chunk (wait-then-bar merge),
// chunk-0/1 prefetch hoisted under the input projection.

typedef unsigned long long u64;

#define B_TOT    32768
#define T_STEPS  79
#define F_IN     16
#define C_DIM    256
#define BM       128      // batch rows per CTA
#define NTHREADS 512      // 16 warps; each warp owns 8 batch rows
#define CHUNK    32       // w rows per smem chunk (32 KB)

// smem: h[128*256] | wbuf0[32*256] | wbuf1[32*256] | w_in[16*256] | xs[16*128]
#define SM_H     0
#define SM_W0    (BM * C_DIM)
#define SM_W1    (SM_W0 + CHUNK * C_DIM)
#define SM_WI    (SM_W1 + CHUNK * C_DIM)
#define SM_XS    (SM_WI + F_IN * C_DIM)
#define SMEM_FLOATS (SM_XS + (NTHREADS / 32) * 8 * F_IN)
#define SMEM_BYTES  (SMEM_FLOATS * 4)          // 221184 B

__device__ __forceinline__ u64 pack2(float lo, float hi) {
    u64 r; asm("mov.b64 %0, {%1, %2};" : "=l"(r) : "f"(lo), "f"(hi)); return r;
}
__device__ __forceinline__ u64 dup2(float v) {
    u64 r; asm("mov.b64 %0, {%1, %1};" : "=l"(r) : "f"(v)); return r;
}
__device__ __forceinline__ void unpack2(u64 v, float& lo, float& hi) {
    asm("mov.b64 {%0, %1}, %2;" : "=f"(lo), "=f"(hi) : "l"(v));
}
__device__ __forceinline__ void fma2(u64& d, u64 a, u64 b) {
    asm("fma.rn.f32x2 %0, %1, %2, %0;" : "+l"(d) : "l"(a), "l"(b));
}

__device__ __forceinline__ void cp16(float* dst, const float* src) {
    unsigned d = (unsigned)__cvta_generic_to_shared(dst);
    asm volatile("cp.async.cg.shared.global [%0], [%1], 16;" :: "r"(d), "l"(src));
}
template <int N> __device__ __forceinline__ void cp_wait() {
    asm volatile("cp.async.wait_group %0;" :: "n"(N));
}

__device__ __forceinline__ void issue_chunk(const float* __restrict__ wglob,
                                            float* __restrict__ buf,
                                            int kc, int tid) {
    const float* src = wglob + kc * CHUNK * C_DIM;
    #pragma unroll
    for (int j = 0; j < 4; ++j)
        cp16(buf + (tid + j * NTHREADS) * 4, src + (tid + j * NTHREADS) * 4);
    asm volatile("cp.async.commit_group;");
}

// Prefetch first two chunks. Caller must have __syncthreads()'d since the
// previous mm_main finished (buffer reuse safety).
__device__ __forceinline__ void mm_begin(const float* __restrict__ wglob,
                                         float* __restrict__ wbuf0,
                                         float* __restrict__ wbuf1, int tid) {
    issue_chunk(wglob, wbuf0, 0, tid);
    issue_chunk(wglob, wbuf1, 1, tid);
}

// acc[b][p] += h[bloc+b][k] * W[k][2*lane + 64*p (+1)]  for k in 0..255.
// Single barrier per chunk: cp_wait<0> + __syncthreads both publishes the
// next chunk and certifies the old buffer consumed, then we refill it.
__device__ __forceinline__ void mm_main(
    const float* __restrict__ wglob,
    float* __restrict__ wbuf0, float* __restrict__ wbuf1,
    const float* __restrict__ hbase,      // h_sm + bloc*C_DIM
    int c2, int tid, u64 acc[8][4])
{
    cp_wait<1>(); __syncthreads();        // chunk 0 ready & visible
    #pragma unroll 1
    for (int kc = 0; kc < 8; ++kc) {
        const float* wc = (kc & 1) ? wbuf1 : wbuf0;
        const float* hk = hbase + kc * CHUNK;
        #pragma unroll 1
        for (int kk2 = 0; kk2 < CHUNK / 2; ++kk2) {
            const float* wr0 = wc + (2 * kk2) * C_DIM + c2;   // lane-contiguous
            const float* wr1 = wr0 + C_DIM;
            u64 wa0 = *(const u64*)(wr0);
            u64 wa1 = *(const u64*)(wr0 + 64);
            u64 wa2 = *(const u64*)(wr0 + 128);
            u64 wa3 = *(const u64*)(wr0 + 192);
            u64 wb0 = *(const u64*)(wr1);
            u64 wb1 = *(const u64*)(wr1 + 64);
            u64 wb2 = *(const u64*)(wr1 + 128);
            u64 wb3 = *(const u64*)(wr1 + 192);
            #pragma unroll
            for (int b = 0; b < 8; ++b) {
                u64 hp = *(const u64*)(hk + b * C_DIM + 2 * kk2);  // bcast LDS.64
                float h0, h1; unpack2(hp, h0, h1);
                u64 hd0 = dup2(h0), hd1 = dup2(h1);
                fma2(acc[b][0], hd0, wa0);
                fma2(acc[b][1], hd0, wa1);
                fma2(acc[b][2], hd0, wa2);
                fma2(acc[b][3], hd0, wa3);
                fma2(acc[b][0], hd1, wb0);
                fma2(acc[b][1], hd1, wb1);
                fma2(acc[b][2], hd1, wb2);
                fma2(acc[b][3], hd1, wb3);
            }
        }
        if (kc < 7) {
            cp_wait<0>(); __syncthreads();   // chunk kc+1 visible; buf kc free
            if (kc + 2 < 8)
                issue_chunk(wglob, (kc & 1) ? wbuf1 : wbuf0, kc + 2, tid);
        }
    }
}

__global__ void __launch_bounds__(NTHREADS, 1)
rnn_fused(const float* __restrict__ x,     const float* __restrict__ w_in,
          const float* __restrict__ w_rec, const float* __restrict__ b_rnn,
          const float* __restrict__ w_d,   const float* __restrict__ b_d,
          float* __restrict__ out)
{
    extern __shared__ float smem[];
    float* h_sm  = smem + SM_H;
    float* wbuf0 = smem + SM_W0;
    float* wbuf1 = smem + SM_W1;
    float* wi_sm = smem + SM_WI;

    const int tid  = threadIdx.x;
    const int lane = tid & 31;
    const int wid  = tid >> 5;
    const int c2   = lane << 1;             // base column; pairs at +0,+64,+128,+192
    const int bloc = wid  << 3;             // 8 batch rows per warp
    const long bglob = (long)blockIdx.x * BM + bloc;
    float* xs_w = smem + SM_XS + wid * (8 * F_IN);   // warp-private x stage

    // stage w_in once (plain row-major)
    {
        const float4* src = (const float4*)w_in;
        float4* dst = (float4*)wi_sm;
        for (int i = tid; i < (F_IN * C_DIM) / 4; i += NTHREADS) dst[i] = src[i];
    }
    u64 bp[4];
    #pragma unroll
    for (int p = 0; p < 4; ++p)
        bp[p] = pack2(b_rnn[c2 + 64*p], b_rnn[c2 + 64*p + 1]);
    __syncthreads();

    u64 acc[8][4];
    const float* hbase = h_sm + bloc * C_DIM;
    const int r = lane >> 2, q = lane & 3;  // x staging: lane holds quad q of row r

    for (int s = 0; s < T_STEPS; ++s) {
        const int t = T_STEPS - 1 - s;      // go_backwards

        // prefetch first two w_rec chunks; latency hides under input proj.
        if (s > 0) {
            __syncthreads();                // all warps out of previous mm_main
            mm_begin(w_rec, wbuf0, wbuf1, tid);
        }

        // ---- stage x[:,t,:] for this warp's 8 rows (warp-private smem) ----
        __syncwarp();                       // prev step's reads done
        {
            const float4 xq = *(const float4*)(x + ((bglob + r) * T_STEPS + t) * F_IN + q * 4);
            *(float4*)(xs_w + r * F_IN + q * 4) = xq;
        }
        __syncwarp();

        // ---- acc = b_rnn + x_t @ w_in (f-pair structure like mm_main) ----
        #pragma unroll
        for (int b = 0; b < 8; ++b)
            #pragma unroll
            for (int p = 0; p < 4; ++p) acc[b][p] = bp[p];

        #pragma unroll 1
        for (int f2 = 0; f2 < F_IN / 2; ++f2) {
            const float* wr0 = wi_sm + (2 * f2) * C_DIM + c2;
            const float* wr1 = wr0 + C_DIM;
            u64 wa0 = *(const u64*)(wr0);
            u64 wa1 = *(const u64*)(wr0 + 64);
            u64 wa2 = *(const u64*)(wr0 + 128);
            u64 wa3 = *(const u64*)(wr0 + 192);
            u64 wb0 = *(const u64*)(wr1);
            u64 wb1 = *(const u64*)(wr1 + 64);
            u64 wb2 = *(const u64*)(wr1 + 128);
            u64 wb3 = *(const u64*)(wr1 + 192);
            #pragma unroll
            for (int b = 0; b < 8; ++b) {
                u64 xp = *(const u64*)(xs_w + b * F_IN + 2 * f2);
                float x0, x1; unpack2(xp, x0, x1);
                u64 xd0 = dup2(x0), xd1 = dup2(x1);
                fma2(acc[b][0], xd0, wa0);
                fma2(acc[b][1], xd0, wa1);
                fma2(acc[b][2], xd0, wa2);
                fma2(acc[b][3], xd0, wa3);
                fma2(acc[b][0], xd1, wb0);
                fma2(acc[b][1], xd1, wb1);
                fma2(acc[b][2], xd1, wb2);
                fma2(acc[b][3], xd1, wb3);
            }
        }

        // ---- recurrent term: acc += h @ w_rec (skip at s=0: h==0) ----
        if (s > 0) mm_main(w_rec, wbuf0, wbuf1, hbase, c2, tid, acc);

        // ---- relu + writeback h (warp-private rows, lane-contiguous STS) ----
        #pragma unroll
        for (int b = 0; b < 8; ++b) {
            float* hrow = h_sm + (bloc + b) * C_DIM + c2;
            #pragma unroll
            for (int p = 0; p < 4; ++p) {
                float lo, hi; unpack2(acc[b][p], lo, hi);
                lo = fmaxf(lo, 0.f); hi = fmaxf(hi, 0.f);
                *(u64*)(hrow + 64*p) = pack2(lo, hi);
            }
        }
    }

    // ---- dense head: out = relu(h_last @ w_d + b_d) ----
    __syncthreads();                        // all warps out of last mm_main
    mm_begin(w_d, wbuf0, wbuf1, tid);

    #pragma unroll
    for (int p = 0; p < 4; ++p)
        bp[p] = pack2(b_d[c2 + 64*p], b_d[c2 + 64*p + 1]);
    #pragma unroll
    for (int b = 0; b < 8; ++b)
        #pragma unroll
        for (int p = 0; p < 4; ++p) acc[b][p] = bp[p];

    mm_main(w_d, wbuf0, wbuf1, hbase, c2, tid, acc);

    #pragma unroll
    for (int b = 0; b < 8; ++b) {
        float* orow = out + (bglob + b) * C_DIM + c2;
        #pragma unroll
        for (int p = 0; p < 4; ++p) {
            float lo, hi; unpack2(acc[b][p], lo, hi);
            float2 v = make_float2(fmaxf(lo, 0.f), fmaxf(hi, 0.f));
            *(float2*)(orow + 64*p) = v;
        }
    }
}

extern "C" void kernel_launch(void* const* d_in, const int* in_sizes, int n_in,
                              void* d_out, int out_size)
{
    const float* x     = (const float*)d_in[0];
    const float* w_in  = (const float*)d_in[1];
    const float* w_rec = (const float*)d_in[2];
    const float* b_rnn = (const float*)d_in[3];
    const float* w_d   = (const float*)d_in[4];
    const float* b_d   = (const float*)d_in[5];
    float* out = (float*)d_out;

    cudaFuncSetAttribute(rnn_fused, cudaFuncAttributeMaxDynamicSharedMemorySize, SMEM_BYTES);

    rnn_fused<<<B_TOT / BM, NTHREADS, SMEM_BYTES>>>(x, w_in, w_rec, b_rnn, w_d, b_d, out);
}

// round 7
// speedup vs baseline: 1.1422x; 1.1422x over previous
#include <cuda_runtime.h>

// RNNBlock: out = relu( RNN_backwards(x; w_in, w_rec, b_rnn) @ w_d + b_d )
// fp32 exact, packed f32x2 FMA. R7: balanced persistent grid (148 CTAs,
// 2 passes of <=112 rows, 7 rows/warp) removes the 256-on-148 wave tax.
// mm pipeline identical to the proven R5 structure.

typedef unsigned long long u64;

#define B_TOT    32768
#define T_STEPS  79
#define F_IN     16
#define C_DIM    256
#define NSM      148      // persistent grid size
#define NTHREADS 512      // 16 warps
#define BW       7        // batch rows per warp
#define PASS_ROWS (16 * BW)   // 112 rows per pass
#define CHUNK    32       // w rows per smem chunk (32 KB)

// smem: h[112*256] | wbuf0[32*256] | wbuf1[32*256] | w_in[16*256] | xs[16*128]
#define SM_H     0
#define SM_W0    (PASS_ROWS * C_DIM)
#define SM_W1    (SM_W0 + CHUNK * C_DIM)
#define SM_WI    (SM_W1 + CHUNK * C_DIM)
#define SM_XS    (SM_WI + F_IN * C_DIM)
#define SMEM_FLOATS (SM_XS + 16 * 8 * F_IN)
#define SMEM_BYTES  (SMEM_FLOATS * 4)          // 204800 B

__device__ __forceinline__ u64 pack2(float lo, float hi) {
    u64 r; asm("mov.b64 %0, {%1, %2};" : "=l"(r) : "f"(lo), "f"(hi)); return r;
}
__device__ __forceinline__ u64 dup2(float v) {
    u64 r; asm("mov.b64 %0, {%1, %1};" : "=l"(r) : "f"(v)); return r;
}
__device__ __forceinline__ void unpack2(u64 v, float& lo, float& hi) {
    asm("mov.b64 {%0, %1}, %2;" : "=f"(lo), "=f"(hi) : "l"(v));
}
__device__ __forceinline__ void fma2(u64& d, u64 a, u64 b) {
    asm("fma.rn.f32x2 %0, %1, %2, %0;" : "+l"(d) : "l"(a), "l"(b));
}

__device__ __forceinline__ void cp16(float* dst, const float* src) {
    unsigned d = (unsigned)__cvta_generic_to_shared(dst);
    asm volatile("cp.async.cg.shared.global [%0], [%1], 16;" :: "r"(d), "l"(src));
}
template <int N> __device__ __forceinline__ void cp_wait() {
    asm volatile("cp.async.wait_group %0;" :: "n"(N));
}

__device__ __forceinline__ void issue_chunk(const float* __restrict__ wglob,
                                            float* __restrict__ buf,
                                            int kc, int tid) {
    const float* src = wglob + kc * CHUNK * C_DIM;
    #pragma unroll
    for (int j = 0; j < 4; ++j)
        cp16(buf + (tid + j * NTHREADS) * 4, src + (tid + j * NTHREADS) * 4);
    asm volatile("cp.async.commit_group;");
}

// acc[b][p] += h[bloc+b][k] * W[k][2*lane + 64*p (+1)]  for k in 0..255.
// W streamed from global in 32-row chunks, double-buffered via cp.async.
// R5-proven pipeline: issue-before-wait, wait<1>, 2 barriers per chunk.
__device__ __forceinline__ void mm256(
    const float* __restrict__ wglob,
    float* __restrict__ wbuf0, float* __restrict__ wbuf1,
    const float* __restrict__ hbase,      // h_sm + bloc*C_DIM
    int c2, int tid, u64 acc[BW][4])
{
    issue_chunk(wglob, wbuf0, 0, tid);
    issue_chunk(wglob, wbuf1, 1, tid);
    #pragma unroll 1
    for (int kc = 0; kc < 8; ++kc) {
        cp_wait<1>();
        __syncthreads();                           // chunk kc visible
        const float* wc = (kc & 1) ? wbuf1 : wbuf0;
        const float* hk = hbase + kc * CHUNK;
        #pragma unroll 2
        for (int kk = 0; kk < CHUNK; ++kk) {
            const float* wr = wc + kk * C_DIM + c2;    // lane-contiguous
            u64 wp0 = *(const u64*)(wr);
            u64 wp1 = *(const u64*)(wr + 64);
            u64 wp2 = *(const u64*)(wr + 128);
            u64 wp3 = *(const u64*)(wr + 192);
            #pragma unroll
            for (int b = 0; b < BW; ++b) {
                u64 hd = dup2(hk[b * C_DIM + kk]);     // warp-broadcast LDS
                fma2(acc[b][0], hd, wp0);
                fma2(acc[b][1], hd, wp1);
                fma2(acc[b][2], hd, wp2);
                fma2(acc[b][3], hd, wp3);
            }
        }
        __syncthreads();                           // buffer kc consumed
        if (kc + 2 < 8) issue_chunk(wglob, (kc & 1) ? wbuf1 : wbuf0, kc + 2, tid);
    }
}

__global__ void __launch_bounds__(NTHREADS, 1)
rnn_fused(const float* __restrict__ x,     const float* __restrict__ w_in,
          const float* __restrict__ w_rec, const float* __restrict__ b_rnn,
          const float* __restrict__ w_d,   const float* __restrict__ b_d,
          float* __restrict__ out)
{
    extern __shared__ float smem[];
    float* h_sm  = smem + SM_H;
    float* wbuf0 = smem + SM_W0;
    float* wbuf1 = smem + SM_W1;
    float* wi_sm = smem + SM_WI;

    const int tid  = threadIdx.x;
    const int lane = tid & 31;
    const int wid  = tid >> 5;
    const int c2   = lane << 1;             // base column; pairs at +0,+64,+128,+192
    const int bloc = wid * BW;              // 7 batch rows per warp
    float* xs_w = smem + SM_XS + wid * (8 * F_IN);   // warp-private x stage

    // balanced contiguous batch range for this CTA (221 or 222 rows)
    const long row_start = ((long)blockIdx.x * B_TOT) / NSM;
    const long row_end   = ((long)(blockIdx.x + 1) * B_TOT) / NSM;

    // stage w_in once (plain row-major)
    {
        const float4* src = (const float4*)w_in;
        float4* dst = (float4*)wi_sm;
        for (int i = tid; i < (F_IN * C_DIM) / 4; i += NTHREADS) dst[i] = src[i];
    }
    u64 brnn[4], bd[4];
    #pragma unroll
    for (int p = 0; p < 4; ++p) {
        brnn[p] = pack2(b_rnn[c2 + 64*p], b_rnn[c2 + 64*p + 1]);
        bd[p]   = pack2(b_d[c2 + 64*p],   b_d[c2 + 64*p + 1]);
    }
    __syncthreads();

    u64 acc[BW][4];
    const float* hbase = h_sm + bloc * C_DIM;
    const int r = lane >> 2, q = lane & 3;  // x staging: lane holds quad q of row r

    #pragma unroll 1
    for (int pass = 0; pass < 2; ++pass) {
        const long rbase = row_start + pass * PASS_ROWS + bloc;  // warp's first row

        #pragma unroll 1
        for (int s = 0; s < T_STEPS; ++s) {
            const int t = T_STEPS - 1 - s;      // go_backwards

            // ---- stage x[:,t,:] for this warp's 7 rows (warp-private smem) ----
            __syncwarp();                       // prev step's reads done
            if (lane < BW * 4) {                // 7 rows x 4 quads = 28 lanes
                long grow = rbase + r;
                if (grow > B_TOT - 1) grow = B_TOT - 1;   // clamp (masked later)
                const float4 xq = *(const float4*)(x + (grow * T_STEPS + t) * F_IN + q * 4);
                *(float4*)(xs_w + r * F_IN + q * 4) = xq;
            }
            __syncwarp();

            // ---- acc = b_rnn + x_t @ w_in ----
            #pragma unroll
            for (int b = 0; b < BW; ++b)
                #pragma unroll
                for (int p = 0; p < 4; ++p) acc[b][p] = brnn[p];

            #pragma unroll 4
            for (int f = 0; f < F_IN; ++f) {
                const float* wr = wi_sm + f * C_DIM + c2;
                u64 wp0 = *(const u64*)(wr);
                u64 wp1 = *(const u64*)(wr + 64);
                u64 wp2 = *(const u64*)(wr + 128);
                u64 wp3 = *(const u64*)(wr + 192);
                #pragma unroll
                for (int b = 0; b < BW; ++b) {
                    u64 xd = dup2(xs_w[b * F_IN + f]);
                    fma2(acc[b][0], xd, wp0);
                    fma2(acc[b][1], xd, wp1);
                    fma2(acc[b][2], xd, wp2);
                    fma2(acc[b][3], xd, wp3);
                }
            }

            // ---- recurrent term: acc += h @ w_rec (skip at s=0: h==0) ----
            if (s > 0) mm256(w_rec, wbuf0, wbuf1, hbase, c2, tid, acc);

            // ---- relu + writeback h (warp-private rows, lane-contiguous) ----
            #pragma unroll
            for (int b = 0; b < BW; ++b) {
                float* hrow = h_sm + (bloc + b) * C_DIM + c2;
                #pragma unroll
                for (int p = 0; p < 4; ++p) {
                    float lo, hi; unpack2(acc[b][p], lo, hi);
                    lo = fmaxf(lo, 0.f); hi = fmaxf(hi, 0.f);
                    *(u64*)(hrow + 64*p) = pack2(lo, hi);
                }
            }
        }

        // ---- dense head: out = relu(h_last @ w_d + b_d), masked store ----
        #pragma unroll
        for (int b = 0; b < BW; ++b)
            #pragma unroll
            for (int p = 0; p < 4; ++p) acc[b][p] = bd[p];

        mm256(w_d, wbuf0, wbuf1, hbase, c2, tid, acc);

        #pragma unroll
        for (int b = 0; b < BW; ++b) {
            const long grow = rbase + b;
            if (grow < row_end) {
                float* orow = out + grow * C_DIM + c2;
                #pragma unroll
                for (int p = 0; p < 4; ++p) {
                    float lo, hi; unpack2(acc[b][p], lo, hi);
                    float2 v = make_float2(fmaxf(lo, 0.f), fmaxf(hi, 0.f));
                    *(float2*)(orow + 64*p) = v;
                }
            }
        }
        // mm256 ended with __syncthreads(): wbufs free; h rewritten next pass
        // only by the owning warp, so no extra barrier needed.
    }
}

extern "C" void kernel_launch(void* const* d_in, const int* in_sizes, int n_in,
                              void* d_out, int out_size)
{
    const float* x     = (const float*)d_in[0];
    const float* w_in  = (const float*)d_in[1];
    const float* w_rec = (const float*)d_in[2];
    const float* b_rnn = (const float*)d_in[3];
    const float* w_d   = (const float*)d_in[4];
    const float* b_d   = (const float*)d_in[5];
    float* out = (float*)d_out;

    cudaFuncSetAttribute(rnn_fused, cudaFuncAttributeMaxDynamicSharedMemorySize, SMEM_BYTES);

    rnn_fused<<<NSM, NTHREADS, SMEM_BYTES>>>(x, w_in, w_rec, b_rnn, w_d, b_d, out);
}